// round 4
// baseline (speedup 1.0000x reference)
#include <cuda_runtime.h>

#define N_BATCH 4
#define KCH 4
#define HS 64
#define WS 64
#define PPTS (HS*WS)              /* 4096 points per batch */
#define NT 128                    /* 32-point warp tiles per batch */
#define JG 32                     /* j-groups of 4 tiles */
#define ITEMS_PER_BATCH (NT*JG)   /* 4096 */
#define TOTAL_ITEMS (N_BATCH*ITEMS_PER_BATCH)
#define GAP2_THRESH 80.0f         /* scaled units: exp2(-40) ~ 1e-12 */

// point record: {fx,fy,fr,fg | fb,h,s0,s1 | s2,s3,0,0}, features pre-scaled by sqrt(log2 e)
__device__ float4 g_pts[N_BATCH * PPTS * 3];
__device__ float4 g_bbox[N_BATCH * NT * 2];   // {minr,ming,minb,maxr | maxg,maxb,-,-}
__device__ double g_acc;
__device__ int    g_work;

__device__ __forceinline__ float ex2f(float a) {
    float r; asm("ex2.approx.ftz.f32 %0, %1;" : "=f"(r) : "f"(a)); return r;
}

__device__ __forceinline__ int morton3(int r, int g, int b) {
    int k = 0;
#pragma unroll
    for (int t = 0; t < 3; t++) {
        k |= ((r >> t) & 1) << (3 * t + 2);
        k |= ((g >> t) & 1) << (3 * t + 1);
        k |= ((b >> t) & 1) << (3 * t + 0);
    }
    return k;
}

// One block per batch: features + 512-bucket counting sort by rgb Morton + tile bboxes.
__global__ void __launch_bounds__(512) prep_kernel(const float* __restrict__ images,
                                                   const float* __restrict__ segs) {
    __shared__ int hist[512];
    __shared__ int sA[512];
    __shared__ int sB[512];
    __shared__ int cur[512];

    int n = blockIdx.x;
    int tid = threadIdx.x;
    if (n == 0 && tid == 0) { g_acc = 0.0; g_work = 0; }

    const float SQL2E = 1.2011224087864498f;   // sqrt(log2(e))
    const float RGBS  = SQL2E / 15.0f;
    const float POSS  = SQL2E / 50.0f;         // SIGMA_XY*SCALE = 50
    const float Q     = 8.0f / (255.0f * RGBS + 1e-3f);  // scaled rgb -> 3-bit cell

    hist[tid] = 0;
    __syncthreads();

    const float* img = images + (size_t)n * 3 * 128 * 128;
    const float* sg  = segs   + (size_t)n * KCH * 128 * 128;

    int keys[8];
#pragma unroll
    for (int k = 0; k < 8; k++) {
        int p = k * 512 + tid;
        int y = p / WS, x = p % WS;
        int ro = (2 * y) * 128 + 2 * x;
        float fr = img[0 * 128 * 128 + ro] * RGBS;
        float fg = img[1 * 128 * 128 + ro] * RGBS;
        float fb = img[2 * 128 * 128 + ro] * RGBS;
        int cr = min(7, (int)(fr * Q));
        int cg = min(7, (int)(fg * Q));
        int cb = min(7, (int)(fb * Q));
        keys[k] = morton3(cr, cg, cb);
        atomicAdd(&hist[keys[k]], 1);
    }
    __syncthreads();

    // inclusive scan over 512 (Hillis-Steele, ping-pong)
    sA[tid] = hist[tid];
    __syncthreads();
    int* src = sA; int* dst = sB;
#pragma unroll
    for (int off = 1; off < 512; off <<= 1) {
        int v = src[tid];
        if (tid >= off) v += src[tid - off];
        dst[tid] = v;
        __syncthreads();
        int* t = src; src = dst; dst = t;
    }
    cur[tid] = src[tid] - hist[tid];   // exclusive start, used as atomic cursor
    __syncthreads();

    // scatter: compute full features, write to sorted slot
    float4* out = g_pts + (size_t)n * PPTS * 3;
#pragma unroll
    for (int k = 0; k < 8; k++) {
        int p = k * 512 + tid;
        int y = p / WS, x = p % WS;
        int ro = (2 * y) * 128 + 2 * x;

        float fx = (float)x * POSS;
        float fy = (float)y * POSS;
        float fr = img[0 * 128 * 128 + ro] * RGBS;
        float fg = img[1 * 128 * 128 + ro] * RGBS;
        float fb = img[2 * 128 * 128 + ro] * RGBS;
        float h = -0.5f * (fx*fx + fy*fy + fr*fr + fg*fg + fb*fb);

        float s[KCH];
#pragma unroll
        for (int c = 0; c < KCH; c++) {
            const float* sk = sg + (size_t)c * 128 * 128;
            s[c] = (sk[ro] + sk[ro + 1] + sk[ro + 128] + sk[ro + 129]) * 0.25f;
        }

        int slot = atomicAdd(&cur[keys[k]], 1);
        out[(size_t)slot * 3 + 0] = make_float4(fx, fy, fr, fg);
        out[(size_t)slot * 3 + 1] = make_float4(fb, h, s[0], s[1]);
        out[(size_t)slot * 3 + 2] = make_float4(s[2], s[3], 0.0f, 0.0f);
    }
    __threadfence();
    __syncthreads();

    // tile bboxes: 16 warps x 8 tiles
    int warp = tid >> 5, lane = tid & 31;
    for (int r = 0; r < 8; r++) {
        int t = warp * 8 + r;
        float4 a = out[(size_t)(t * 32 + lane) * 3 + 0];
        float4 b = out[(size_t)(t * 32 + lane) * 3 + 1];
        float mr = a.z, mg = a.w, mb = b.x;
        float Mr = mr, Mg = mg, Mb = mb;
#pragma unroll
        for (int off = 16; off > 0; off >>= 1) {
            mr = fminf(mr, __shfl_down_sync(0xFFFFFFFFu, mr, off));
            mg = fminf(mg, __shfl_down_sync(0xFFFFFFFFu, mg, off));
            mb = fminf(mb, __shfl_down_sync(0xFFFFFFFFu, mb, off));
            Mr = fmaxf(Mr, __shfl_down_sync(0xFFFFFFFFu, Mr, off));
            Mg = fmaxf(Mg, __shfl_down_sync(0xFFFFFFFFu, Mg, off));
            Mb = fmaxf(Mb, __shfl_down_sync(0xFFFFFFFFu, Mb, off));
        }
        if (lane == 0) {
            g_bbox[(size_t)(n * NT + t) * 2 + 0] = make_float4(mr, mg, mb, Mr);
            g_bbox[(size_t)(n * NT + t) * 2 + 1] = make_float4(Mg, Mb, 0.0f, 0.0f);
        }
    }
}

__global__ void __launch_bounds__(256) crf_kernel() {
    float wacc = 0.0f;

    for (;;) {
        int item;
        if ((threadIdx.x & 31) == 0) item = atomicAdd(&g_work, 1);
        item = __shfl_sync(0xFFFFFFFFu, item, 0);
        if (item >= TOTAL_ITEMS) break;

        int n  = item >> 12;
        int r  = item & 4095;
        int i  = r >> 5;          // p tile
        int jg = r & 31;          // j group of 4
        if (jg * 4 + 3 < i) continue;

        const float4* base = g_pts + (size_t)n * PPTS * 3;
        int lane = threadIdx.x & 31;

        const float4* pp = base + (size_t)(i * 32 + lane) * 3;
        float4 A = pp[0], B = pp[1], C = pp[2];
        float pfx = A.x, pfy = A.y, pfr = A.z, pfg = A.w, pfb = B.x, ph = B.y;
        float ps0 = B.z, ps1 = B.w, ps2 = C.x, ps3 = C.y;

        float4 bi0 = __ldg(&g_bbox[(size_t)(n * NT + i) * 2 + 0]);
        float4 bi1 = __ldg(&g_bbox[(size_t)(n * NT + i) * 2 + 1]);
        // bi: min(r,g,b)=bi0.xyz  max(r)=bi0.w  max(g,b)=bi1.xy

#pragma unroll
        for (int dj = 0; dj < 4; dj++) {
            int j = jg * 4 + dj;
            if (j < i) continue;

            float4 bj0 = __ldg(&g_bbox[(size_t)(n * NT + j) * 2 + 0]);
            float4 bj1 = __ldg(&g_bbox[(size_t)(n * NT + j) * 2 + 1]);

            float gr = fmaxf(fmaxf(bj0.x - bi0.w, bi0.x - bj0.w), 0.0f);
            float gg = fmaxf(fmaxf(bj0.y - bi1.x, bi0.y - bj1.x), 0.0f);
            float gb = fmaxf(fmaxf(bj0.z - bi1.y, bi0.z - bj1.y), 0.0f);
            float gap2 = gr * gr + gg * gg + gb * gb;
            if (gap2 > GAP2_THRESH) continue;

            const float4* qb = base + (size_t)j * 32 * 3;
            float jacc = 0.0f;
#pragma unroll 2
            for (int q = 0; q < 32; q++) {
                float4 a = __ldg(qb + q * 3 + 0);
                float4 b = __ldg(qb + q * 3 + 1);
                float4 c = __ldg(qb + q * 3 + 2);
                float arg = ph + b.y;
                arg = fmaf(pfx, a.x, arg);
                arg = fmaf(pfy, a.y, arg);
                arg = fmaf(pfr, a.z, arg);
                arg = fmaf(pfg, a.w, arg);
                arg = fmaf(pfb, b.x, arg);
                float t = ps0 * b.z;
                t = fmaf(ps1, b.w, t);
                t = fmaf(ps2, c.x, t);
                t = fmaf(ps3, c.y, t);
                jacc = fmaf(ex2f(arg), t, jacc);
            }
            wacc += (j == i) ? jacc : 2.0f * jacc;
        }
    }

    // warp reduce + one atomic per warp
#pragma unroll
    for (int off = 16; off > 0; off >>= 1)
        wacc += __shfl_down_sync(0xFFFFFFFFu, wacc, off);
    if ((threadIdx.x & 31) == 0 && wacc != 0.0f)
        atomicAdd(&g_acc, (double)wacc);
}

__global__ void finish_kernel(float* __restrict__ out) {
    out[0] = (float)(g_acc * (-1e-7 / (double)N_BATCH));
}

extern "C" void kernel_launch(void* const* d_in, const int* in_sizes, int n_in,
                              void* d_out, int out_size) {
    const float* images = (const float*)d_in[0];
    const float* segs   = (const float*)d_in[1];

    prep_kernel<<<N_BATCH, 512>>>(images, segs);
    crf_kernel<<<296, 256>>>();
    finish_kernel<<<1, 1>>>((float*)d_out);
}

// round 6
// speedup vs baseline: 2.3591x; 2.3591x over previous
#include <cuda_runtime.h>

#define N_BATCH 4
#define KCH 4
#define HS 64
#define WS 64
#define PPTS (HS*WS)            /* 4096 points per batch */
#define TILE 256
#define NTILES (PPTS/TILE)      /* 16 */
#define NPAIRS (NTILES*(NTILES+1)/2)   /* 136 upper-triangle tile pairs */
#define BLOCK 256
#define TOTALB (NPAIRS*N_BATCH)

// point record: {fx,fy,fr,fg | fb,h,s0,s1 | s2,s3,0,0}, features pre-scaled by sqrt(log2 e)
__device__ float4 g_pts[N_BATCH * PPTS * 3];
__device__ double g_acc;
__device__ unsigned int g_done;

__device__ __forceinline__ float ex2f(float a) {
    float r; asm("ex2.approx.ftz.f32 %0, %1;" : "=f"(r) : "f"(a)); return r;
}

__global__ void prep_kernel(const float* __restrict__ images,
                            const float* __restrict__ segs) {
    int idx = blockIdx.x * blockDim.x + threadIdx.x;
    if (idx == 0) { g_acc = 0.0; g_done = 0u; }
    if (idx >= N_BATCH * PPTS) return;
    int n = idx / PPTS;
    int p = idx % PPTS;
    int y = p / WS;
    int x = p % WS;

    const float SQL2E = 1.2011224087864498f;   // sqrt(log2(e))

    float fx = (float)x * (SQL2E / 50.0f);     // SIGMA_XY*SCALE = 50
    float fy = (float)y * (SQL2E / 50.0f);

    const float* img = images + (size_t)n * 3 * 128 * 128;
    int ro = (2 * y) * 128 + 2 * x;
    float fr = img[0 * 128 * 128 + ro] * (SQL2E / 15.0f);
    float fg = img[1 * 128 * 128 + ro] * (SQL2E / 15.0f);
    float fb = img[2 * 128 * 128 + ro] * (SQL2E / 15.0f);

    float sq = fx*fx + fy*fy + fr*fr + fg*fg + fb*fb;
    float h = -0.5f * sq;

    const float* sg = segs + (size_t)n * KCH * 128 * 128;
    float s[KCH];
#pragma unroll
    for (int k = 0; k < KCH; k++) {
        const float* sk = sg + (size_t)k * 128 * 128;
        s[k] = (sk[ro] + sk[ro + 1] + sk[ro + 128] + sk[ro + 129]) * 0.25f;
    }

    float4* o = g_pts + (size_t)idx * 3;
    o[0] = make_float4(fx, fy, fr, fg);
    o[1] = make_float4(fb, h, s[0], s[1]);
    o[2] = make_float4(s[2], s[3], 0.0f, 0.0f);
}

__global__ void __launch_bounds__(BLOCK) crf_kernel(float* __restrict__ out) {
    __shared__ float4 tile[TILE * 3];    // 12 KB
    __shared__ float wsum[BLOCK / 32];

    // Decode upper-triangle pair index t -> (I, J), J >= I.
    int t = blockIdx.x;
    int n = blockIdx.y;
    float ft = (float)t;
    int I = (int)((2.0f * NTILES + 1.0f - sqrtf((2.0f * NTILES + 1.0f) * (2.0f * NTILES + 1.0f) - 8.0f * ft)) * 0.5f);
    // exact correction (I off by at most 1 from float sqrt)
    while (I * NTILES - (I * (I - 1)) / 2 > t) I--;
    while ((I + 1) * NTILES - ((I + 1) * I) / 2 <= t) I++;
    int J = I + (t - (I * NTILES - (I * (I - 1)) / 2));

    const float4* base = g_pts + (size_t)n * PPTS * 3;

    // Cooperative load of q tile J (256 points * 3 float4)
    for (int i = threadIdx.x; i < TILE * 3; i += BLOCK)
        tile[i] = base[(size_t)J * TILE * 3 + i];

    // Own point p = I*TILE + tid
    int p = I * TILE + threadIdx.x;
    float4 A = base[(size_t)p * 3 + 0];
    float4 B = base[(size_t)p * 3 + 1];
    float4 C = base[(size_t)p * 3 + 2];
    float pfx = A.x, pfy = A.y, pfr = A.z, pfg = A.w, pfb = B.x, ph = B.y;
    float ps0 = B.z, ps1 = B.w, ps2 = C.x, ps3 = C.y;

    __syncthreads();

    float acc0 = 0.0f, acc1 = 0.0f;
#pragma unroll 4
    for (int j = 0; j < TILE; j += 2) {
        {
            float4 a = tile[j * 3 + 0];
            float4 b = tile[j * 3 + 1];
            float4 c = tile[j * 3 + 2];
            float arg = ph + b.y;
            arg = fmaf(pfx, a.x, arg);
            arg = fmaf(pfy, a.y, arg);
            arg = fmaf(pfr, a.z, arg);
            arg = fmaf(pfg, a.w, arg);
            arg = fmaf(pfb, b.x, arg);
            float s = ps0 * b.z;
            s = fmaf(ps1, b.w, s);
            s = fmaf(ps2, c.x, s);
            s = fmaf(ps3, c.y, s);
            acc0 = fmaf(ex2f(arg), s, acc0);
        }
        {
            float4 a = tile[(j + 1) * 3 + 0];
            float4 b = tile[(j + 1) * 3 + 1];
            float4 c = tile[(j + 1) * 3 + 2];
            float arg = ph + b.y;
            arg = fmaf(pfx, a.x, arg);
            arg = fmaf(pfy, a.y, arg);
            arg = fmaf(pfr, a.z, arg);
            arg = fmaf(pfg, a.w, arg);
            arg = fmaf(pfb, b.x, arg);
            float s = ps0 * b.z;
            s = fmaf(ps1, b.w, s);
            s = fmaf(ps2, c.x, s);
            s = fmaf(ps3, c.y, s);
            acc1 = fmaf(ex2f(arg), s, acc1);
        }
    }

    float acc = acc0 + acc1;
    if (I != J) acc *= 2.0f;    // symmetric off-diagonal tile counted twice

    // Warp + block reduce
#pragma unroll
    for (int off = 16; off > 0; off >>= 1)
        acc += __shfl_down_sync(0xFFFFFFFFu, acc, off);
    int lane = threadIdx.x & 31;
    int warp = threadIdx.x >> 5;
    if (lane == 0) wsum[warp] = acc;
    __syncthreads();
    if (threadIdx.x == 0) {
        float s = 0.0f;
#pragma unroll
        for (int i = 0; i < BLOCK / 32; i++) s += wsum[i];
        atomicAdd(&g_acc, (double)s);
        __threadfence();
        unsigned int d = atomicAdd(&g_done, 1u);
        if (d == TOTALB - 1u) {
            // last block: finalize. loss = WEIGHT * (-sum / N_BATCH)
            double total = *((volatile double*)&g_acc);
            out[0] = (float)(total * (-1e-7 / (double)N_BATCH));
        }
    }
}

extern "C" void kernel_launch(void* const* d_in, const int* in_sizes, int n_in,
                              void* d_out, int out_size) {
    const float* images = (const float*)d_in[0];
    const float* segs   = (const float*)d_in[1];

    prep_kernel<<<(N_BATCH * PPTS + 255) / 256, 256>>>(images, segs);

    dim3 grid(NPAIRS, N_BATCH);
    crf_kernel<<<grid, BLOCK>>>((float*)d_out);
}